// round 17
// baseline (speedup 1.0000x reference)
#include <cuda_runtime.h>
#include <math.h>

#define BATCH   64
#define VDIM    16384
#define FDIM    32
#define NSPLIT  8
#define ROWS_PER_SPLIT (VDIM / NSPLIT)          // 2048
#define GROUPS_PER_SPLIT (ROWS_PER_SPLIT / 4)   // 512 (4-row groups)
#define NGROUPS (VDIM / 4)                       // 4096 per batch
#define PDEPTH  6

// Deterministic scratch (no float atomics): [B][NSPLIT][2][F]
__device__ float g_scratch[BATCH * NSPLIT * 2 * FDIM];

// ---------------------------------------------------------------------------
// Pass 1: split reduction. 512 blocks @ 4/SM (single wave) with 64 regs ->
// genuine depth-6 software pipeline, ~12 loads in flight per warp.
// Lane l: row-in-group r = l/8, quad q = l%8 (columns 4q..4q+3).
// ---------------------------------------------------------------------------
__global__ void __launch_bounds__(256, 4)
reduce_kernel(const float4* __restrict__ fracs, const float2* __restrict__ feats)
{
    const int b     = blockIdx.y;
    const int split = blockIdx.x;
    const int lane  = threadIdx.x & 31;
    const int warp  = threadIdx.x >> 5;
    const int q     = lane & 7;
    const int r     = lane >> 3;

    const float4* __restrict__ fb = fracs + (size_t)b * VDIM * 8;  // 8 float4/row
    const float2* __restrict__ eb = feats + (size_t)b * VDIM * 2;  // 2 float2/row
    const int g0 = split * GROUPS_PER_SPLIT;

    const int NITER = GROUPS_PER_SPLIT / 8;    // 64 iterations per warp
    #define VROW(it)  ((g0 + warp + (it) * 8) * 4 + r)

    float4 s  = make_float4(0.f, 0.f, 0.f, 0.f);
    float4 ws = make_float4(0.f, 0.f, 0.f, 0.f);

    // depth-6 software pipeline (fits in the 64-reg budget)
    float4 xb[PDEPTH];
    float2 fbuf[PDEPTH];
    #pragma unroll
    for (int p = 0; p < PDEPTH; p++) {
        xb[p]   = __ldcs(fb + (size_t)VROW(p) * 8 + q);
        fbuf[p] = __ldcs(eb + (size_t)VROW(p) * 2);
    }

    #pragma unroll 6
    for (int it = 0; it < NITER; ++it) {
        const int p = it % PDEPTH;
        float4 x  = xb[p];
        float2 ee = fbuf[p];
        if (it + PDEPTH < NITER) {
            xb[p]   = __ldcs(fb + (size_t)VROW(it + PDEPTH) * 8 + q);
            fbuf[p] = __ldcs(eb + (size_t)VROW(it + PDEPTH) * 2);
        }
        const float e  = ee.x;
        const float ew = ee.x * ee.y;
        s.x  += e  * x.x;  s.y  += e  * x.y;  s.z  += e  * x.z;  s.w  += e  * x.w;
        ws.x += ew * x.x;  ws.y += ew * x.y;  ws.z += ew * x.z;  ws.w += ew * x.w;
    }
    #undef VROW

    // fold the 4 row-groups: xor-shuffle over lane bits 3,4 (fixed order).
    #pragma unroll
    for (int off = 8; off <= 16; off <<= 1) {
        s.x  += __shfl_xor_sync(0xffffffffu, s.x,  off);
        s.y  += __shfl_xor_sync(0xffffffffu, s.y,  off);
        s.z  += __shfl_xor_sync(0xffffffffu, s.z,  off);
        s.w  += __shfl_xor_sync(0xffffffffu, s.w,  off);
        ws.x += __shfl_xor_sync(0xffffffffu, ws.x, off);
        ws.y += __shfl_xor_sync(0xffffffffu, ws.y, off);
        ws.z += __shfl_xor_sync(0xffffffffu, ws.z, off);
        ws.w += __shfl_xor_sync(0xffffffffu, ws.w, off);
    }

    __shared__ float smS[8][FDIM];
    __shared__ float smW[8][FDIM];
    if (r == 0) {                    // lanes 0..7 hold totals for quad q
        *reinterpret_cast<float4*>(&smS[warp][q * 4]) = s;
        *reinterpret_cast<float4*>(&smW[warp][q * 4]) = ws;
    }
    __syncthreads();

    if (warp == 0) {
        float a = 0.f, wa = 0.f;
        #pragma unroll
        for (int w = 0; w < 8; w++) {
            a  += smS[w][lane];
            wa += smW[w][lane];
        }
        float* dst = g_scratch + (size_t)(b * NSPLIT + split) * 2 * FDIM;
        dst[lane]        = a;
        dst[FDIM + lane] = wa;
    }
}

// ---------------------------------------------------------------------------
// Pass 2 (fused sort + permute):
//  - warp 0 computes weighted etas (fixed split order -> deterministic) and
//    the stable counting-rank matching jax.lax.top_k(-we) tie semantics;
//    stores the FORWARD permutation: out col k <- src col perm[k].
//  - all warps permute via smem tile: LDG.128 -> STS.128 -> 4x LDS.32
//    (register-resident perm) -> STG.128 of contiguous output columns.
// ---------------------------------------------------------------------------
__global__ void __launch_bounds__(256)
gather_kernel(const float4* __restrict__ fracs, float4* __restrict__ out)
{
    __shared__ int   s_perm[FDIM];
    __shared__ float stg[8][2][4][36];   // per-warp double-buffered 4x32 tile (+pad)

    const int b = blockIdx.y;

    if (threadIdx.x < 32) {
        const int f = threadIdx.x;
        float s = 0.f, ws = 0.f;
        #pragma unroll
        for (int sp = 0; sp < NSPLIT; sp++) {
            const float* src = g_scratch + (size_t)(b * NSPLIT + sp) * 2 * FDIM;
            s  += src[f];
            ws += src[FDIM + f];
        }
        float we = ws / (s + 1e-7f);
        we = (fabsf(we) > 0.1f) ? we : 500.0f;

        // rank = #{j : we_j < we_f or (we_j == we_f and j < f)} (stable asc.)
        int rank = 0;
        #pragma unroll
        for (int j = 0; j < FDIM; j++) {
            float wj = __shfl_sync(0xffffffffu, we, j);
            rank += (int)((wj < we) || (wj == we && j < f));
        }
        s_perm[rank] = f;                // forward perm
    }
    __syncthreads();

    const int lane = threadIdx.x & 31;
    const int warp = threadIdx.x >> 5;
    const int q    = lane & 7;
    const int r    = lane >> 3;
    const int wi   = blockIdx.x * 8 + warp;
    const int nw   = gridDim.x * 8;

    // source columns feeding this lane's contiguous output quad 4q..4q+3
    const int4 pk = *reinterpret_cast<const int4*>(&s_perm[4 * q]);

    const float4* __restrict__ src = fracs + (size_t)b * VDIM * 8;
    float4*       __restrict__ dst = out   + (size_t)b * VDIM * 8;

    #define GADDR(g) ((size_t)((g) * 4 + r) * 8 + q)

    int g_cur = wi;
    float4 x0, x1;
    if (g_cur < NGROUPS)       x0 = __ldcs(src + GADDR(g_cur));
    if (g_cur + nw < NGROUPS)  x1 = __ldcs(src + GADDR(g_cur + nw));

    for (; g_cur < NGROUPS; g_cur += nw) {
        float4 xn;
        if (g_cur + 2 * nw < NGROUPS) xn = __ldcs(src + GADDR(g_cur + 2 * nw));
        const int buf = (g_cur / nw) & 1;
        *reinterpret_cast<float4*>(&stg[warp][buf][r][4 * q]) = x0;
        __syncwarp();
        float4 y;
        y.x = stg[warp][buf][r][pk.x];
        y.y = stg[warp][buf][r][pk.y];
        y.z = stg[warp][buf][r][pk.z];
        y.w = stg[warp][buf][r][pk.w];
        __stcs(dst + GADDR(g_cur), y);   // STG.128, fully coalesced
        x0 = x1; x1 = xn;
    }
    #undef GADDR
}

// ---------------------------------------------------------------------------
extern "C" void kernel_launch(void* const* d_in, const int* in_sizes, int n_in,
                              void* d_out, int out_size)
{
    const float4* fracs = (const float4*)d_in[0];   // [64,16384,32] f32
    const float2* feats = (const float2*)d_in[1];   // [64,16384,4]  f32
    float4*       out   = (float4*)d_out;           // [64,16384,32] f32

    dim3 g1(NSPLIT, BATCH);    // 512 blocks @ 4/SM — single wave, 64 regs
    reduce_kernel<<<g1, 256>>>(fracs, feats);

    dim3 g2(18, BATCH);        // 1152 blocks — single wave
    gather_kernel<<<g2, 256>>>(fracs, out);
}